// round 15
// baseline (speedup 1.0000x reference)
#include <cuda_runtime.h>
#include <math.h>
#include <stddef.h>

#define Bn  4
#define Cn  256
#define Hn  128
#define Wn  128
#define HWn (Hn*Wn)
#define WFn 65
#define Fn  (Hn*WFn)     // 8320, compressed spectral tile [128][65]
#define NBn 6
#define GHn 128
#define P   65           // smem float2 row stride
#define NT  512

typedef unsigned long long u64;

// ---------------- scratch -----------------------------------------------------
__device__ float  g_xt  [Bn*Cn*HWn];
__device__ float  g_spec[Bn*Cn*HWn];
__device__ float2 g_Xf  [Bn*Cn*Fn];    // compressed-brev layout [h][cc]
__device__ float2 g_Xm  [Bn*Cn*Fn];
__device__ float  g_alpha[Bn*Cn*NBn];
__device__ float  g_lwT [Cn*Cn];
__device__ int    g_bandid[Fn];
__device__ float  g_binv[NBn];
__device__ int    g_kxi, g_kyi;

__device__ __forceinline__ int brev7(int i) { return (int)(__brev((unsigned)i) >> 25); }

__device__ __forceinline__ float2 cmul(float2 a, float2 w) {
    return make_float2(a.x*w.x - a.y*w.y, a.x*w.y + a.y*w.x);
}
__device__ __forceinline__ float2 cadd(float2 a, float2 b){ return make_float2(a.x+b.x, a.y+b.y); }
__device__ __forceinline__ float2 csub(float2 a, float2 b){ return make_float2(a.x-b.x, a.y-b.y); }
__device__ __forceinline__ float2 shflx(float2 v, int m) {
    return make_float2(__shfl_xor_sync(0xffffffffu, v.x, m),
                       __shfl_xor_sync(0xffffffffu, v.y, m));
}

struct LaneTw { float2 t128a, t128b, t64, t32, t16, t8, t4; };

__device__ __forceinline__ LaneTw load_lane_tw(const float2* tw, int l) {
    LaneTw T;
    T.t128a = tw[l];
    T.t128b = cmul(tw[l], tw[32]);
    T.t64 = tw[2*l];
    T.t32 = tw[4*(l&15)];
    T.t16 = tw[8*(l&7)];
    T.t8  = tw[16*(l&3)];
    T.t4  = tw[32*(l&1)];
    return T;
}

// DIF-128: natural input (n = 32q+l), output position n holds X[brev7(n)]
__device__ __forceinline__ void fft128_dif(float2& x0, float2& x1, float2& x2, float2& x3,
                                           const LaneTw& T, int l) {
    { float2 u=x0, v=x2; x0=cadd(u,v); x2=cmul(csub(u,v), T.t128a);
      u=x1; v=x3;        x1=cadd(u,v); x3=cmul(csub(u,v), T.t128b); }
    { float2 u=x0, v=x1; x0=cadd(u,v); x1=cmul(csub(u,v), T.t64);
      u=x2; v=x3;        x2=cadd(u,v); x3=cmul(csub(u,v), T.t64); }
#define DIF_STAGE(mask, twv) { float2 p; \
    p = shflx(x0, mask); x0 = (l & mask) ? cmul(csub(p,x0), twv) : cadd(x0,p); \
    p = shflx(x1, mask); x1 = (l & mask) ? cmul(csub(p,x1), twv) : cadd(x1,p); \
    p = shflx(x2, mask); x2 = (l & mask) ? cmul(csub(p,x2), twv) : cadd(x2,p); \
    p = shflx(x3, mask); x3 = (l & mask) ? cmul(csub(p,x3), twv) : cadd(x3,p); }
    DIF_STAGE(16, T.t32)
    DIF_STAGE(8,  T.t16)
    DIF_STAGE(4,  T.t8)
    DIF_STAGE(2,  T.t4)
#undef DIF_STAGE
    { float2 p;
      p = shflx(x0,1); x0 = (l&1) ? csub(p,x0) : cadd(x0,p);
      p = shflx(x1,1); x1 = (l&1) ? csub(p,x1) : cadd(x1,p);
      p = shflx(x2,1); x2 = (l&1) ? csub(p,x2) : cadd(x2,p);
      p = shflx(x3,1); x3 = (l&1) ? csub(p,x3) : cadd(x3,p); }
}

// DIT-128: input position n holds x[brev7(n)], output position n holds X[n]
__device__ __forceinline__ void fft128_dit(float2& x0, float2& x1, float2& x2, float2& x3,
                                           const LaneTw& T, int l) {
    { float2 p;
      p = shflx(x0,1); x0 = (l&1) ? csub(p,x0) : cadd(x0,p);
      p = shflx(x1,1); x1 = (l&1) ? csub(p,x1) : cadd(x1,p);
      p = shflx(x2,1); x2 = (l&1) ? csub(p,x2) : cadd(x2,p);
      p = shflx(x3,1); x3 = (l&1) ? csub(p,x3) : cadd(x3,p); }
#define DIT_STAGE(mask, twv) { float2 p; \
    p = shflx(x0, mask); x0 = (l & mask) ? csub(p, cmul(x0,twv)) : cadd(x0, cmul(p,twv)); \
    p = shflx(x1, mask); x1 = (l & mask) ? csub(p, cmul(x1,twv)) : cadd(x1, cmul(p,twv)); \
    p = shflx(x2, mask); x2 = (l & mask) ? csub(p, cmul(x2,twv)) : cadd(x2, cmul(p,twv)); \
    p = shflx(x3, mask); x3 = (l & mask) ? csub(p, cmul(x3,twv)) : cadd(x3, cmul(p,twv)); }
    DIT_STAGE(2,  T.t4)
    DIT_STAGE(4,  T.t8)
    DIT_STAGE(8,  T.t16)
    DIT_STAGE(16, T.t32)
#undef DIT_STAGE
    { float2 v = cmul(x1, T.t64); x1 = csub(x0,v); x0 = cadd(x0,v);
      v = cmul(x3, T.t64);        x3 = csub(x2,v); x2 = cadd(x2,v); }
    { float2 v = cmul(x2, T.t128a); x2 = csub(x0,v); x0 = cadd(x0,v);
      v = cmul(x3, T.t128b);        x3 = csub(x1,v); x1 = cadd(x1,v); }
}

// packed f32x2 helpers
__device__ __forceinline__ u64 pk2(float lo, float hi) {
    u64 r; asm("mov.b64 %0, {%1,%2};" : "=l"(r) : "f"(lo), "f"(hi)); return r;
}
__device__ __forceinline__ float2 upk2(u64 v) {
    float lo, hi; asm("mov.b64 {%0,%1}, %2;" : "=f"(lo), "=f"(hi) : "l"(v));
    return make_float2(lo, hi);
}
#define FMA2(d, a, b, c) asm("fma.rn.f32x2 %0, %1, %2, %3;" : "=l"(d) : "l"(a), "l"(b), "l"(c))

// ---------------- K0a: band table (compressed layout) + mask extents ----------
__global__ void k0_bands(const float* __restrict__ kx, const float* __restrict__ ky) {
    __shared__ float cnt[NBn];
    int tid = threadIdx.x;
    if (tid < NBn) cnt[tid] = 0.f;
    __syncthreads();
    for (int f = tid; f < Fn; f += blockDim.x) {
        int hy = f / 65, cc = f % 65;
        int wx = (cc == 64) ? 64 : brev7(2*cc);
        float yy = __fdiv_rn((float)hy, 127.0f);
        float xx = __fdiv_rn((float)wx, 64.0f);
        float r  = __fsqrt_rn(__fadd_rn(__fmul_rn(yy,yy), __fmul_rn(xx,xx)));
        float rmax = __fadd_rn(__fsqrt_rn(2.0f), 1e-8f);
        float rn = __fdiv_rn(r, rmax);
        int bid = (int)floorf(__fmul_rn(rn, 6.0f));
        if (bid > NBn-1) bid = NBn-1;
        g_bandid[f] = bid;
        atomicAdd(&cnt[bid], 1.0f);
    }
    __syncthreads();
    if (tid < NBn) g_binv[tid] = 1.0f / (fmaxf(cnt[tid], 1.0f) + 1e-6f);
    if (tid == 0) {
        float sx = 1.0f / (1.0f + expf(-kx[0]));
        float sy = 1.0f / (1.0f + expf(-ky[0]));
        g_kxi = (int)floorf(sx * (float)Hn);
        g_kyi = (int)floorf(sy * (float)WFn);
    }
}

// ---------------- K0b: lin_w transpose ----------------------------------------
__global__ void k_trw(const float* __restrict__ lin_w) {
    __shared__ float tile[32][33];
    int c0 = blockIdx.x * 32, d0 = blockIdx.y * 32;
    int tx = threadIdx.x, ty = threadIdx.y;
    #pragma unroll
    for (int k = 0; k < 32; k += 8)
        tile[ty+k][tx] = lin_w[(c0+ty+k)*Cn + d0+tx];
    __syncthreads();
    #pragma unroll
    for (int k = 0; k < 32; k += 8)
        g_lwT[(d0+ty+k)*Cn + c0+tx] = tile[tx][ty+k];
}

// ---------------- K_tr: (b,p,c) -> (b,c,p) ------------------------------------
__global__ void k_tr(const float* __restrict__ x) {
    __shared__ float tile[32][33];
    int b  = blockIdx.z;
    int c0 = blockIdx.x * 32, p0 = blockIdx.y * 32;
    int tx = threadIdx.x, ty = threadIdx.y;
    #pragma unroll
    for (int k = 0; k < 32; k += 8)
        tile[ty+k][tx] = x[((size_t)b*HWn + p0+ty+k)*Cn + c0+tx];
    __syncthreads();
    #pragma unroll
    for (int k = 0; k < 32; k += 8)
        g_xt[((size_t)b*Cn + c0+ty+k)*HWn + p0+tx] = tile[tx][ty+k];
}

// ---------------- K1: forward rfft2 (warp-register FFT) + fused band gate -----
__global__ void __launch_bounds__(NT, 2)
k1_fft(const float* __restrict__ w1p, const float* __restrict__ b1,
       const float* __restrict__ w2p, const float* __restrict__ b2) {
    extern __shared__ float2 Z[];          // [128][P]
    __shared__ float2 tw[64];
    __shared__ float  bsum[NBn];
    __shared__ float  m6[NBn];
    __shared__ float  hbuf[GHn];
    int tid = threadIdx.x;
    int l = tid & 31, w = tid >> 5;
    int bc = blockIdx.x;

    if (tid < 64) {
        float ang = -2.0f*3.14159265358979323846f*(float)tid/128.0f;
        float s, c; sincosf(ang, &s, &c);
        tw[tid] = make_float2(c, s);
    }
    if (tid < NBn) bsum[tid] = 0.f;
    __syncthreads();
    LaneTw T = load_lane_tw(tw, l);

    // row FFTs (DIF): natural gmem row -> compressed store at row brev7(r)
    const float* src0 = g_xt + (size_t)bc*HWn;
    #pragma unroll
    for (int i = 0; i < 8; i++) {
        int r = w + 16*i;
        const float* src = src0 + r*128;
        float2 x0 = make_float2(src[l],      0.f);
        float2 x1 = make_float2(src[32 + l], 0.f);
        float2 x2 = make_float2(src[64 + l], 0.f);
        float2 x3 = make_float2(src[96 + l], 0.f);
        fft128_dif(x0, x1, x2, x3, T, l);
        float2* zr = Z + brev7(r)*P;
        if (!(l & 1)) {
            int c0 = l >> 1;
            zr[c0]      = x0;
            zr[16 + c0] = x1;
            zr[32 + c0] = x2;
            zr[48 + c0] = x3;
        } else if (l == 1) {
            zr[64] = x0;
        }
    }
    __syncthreads();

    // column FFTs (DIT): brev rows in, natural out
    for (int cc = w; cc < 65; cc += 16) {
        float2 x0 = Z[(l      )*P + cc];
        float2 x1 = Z[(32 + l )*P + cc];
        float2 x2 = Z[(64 + l )*P + cc];
        float2 x3 = Z[(96 + l )*P + cc];
        fft128_dit(x0, x1, x2, x3, T, l);
        Z[(l      )*P + cc] = x0;
        Z[(32 + l )*P + cc] = x1;
        Z[(64 + l )*P + cc] = x2;
        Z[(96 + l )*P + cc] = x3;
    }
    __syncthreads();

    // store spectrum + per-band |Xf| sums
    const float sc = 1.0f/128.0f;
    float s6[NBn];
    #pragma unroll
    for (int n = 0; n < NBn; n++) s6[n] = 0.f;
    #pragma unroll
    for (int it = 0; it < (Fn + NT-1)/NT; it++) {
        int i = tid + it*NT;
        if (i < Fn) {
            float2 v = Z[i];
            v.x *= sc; v.y *= sc;
            g_Xf[(size_t)bc*Fn + i] = v;
            float mag = sqrtf(v.x*v.x + v.y*v.y);
            int bid = g_bandid[i];
            #pragma unroll
            for (int n = 0; n < NBn; n++) s6[n] += (bid == n) ? mag : 0.f;
        }
    }
    #pragma unroll
    for (int off = 16; off > 0; off >>= 1)
        #pragma unroll
        for (int n = 0; n < NBn; n++)
            s6[n] += __shfl_xor_sync(0xffffffffu, s6[n], off);
    if (l == 0)
        #pragma unroll
        for (int n = 0; n < NBn; n++) atomicAdd(&bsum[n], s6[n]);
    __syncthreads();

    if (tid < NBn) m6[tid] = bsum[tid] * g_binv[tid];
    __syncthreads();
    if (tid < GHn) {
        float acc = b1[tid];
        #pragma unroll
        for (int n = 0; n < NBn; n++) acc += m6[n] * w1p[tid*NBn + n];
        hbuf[tid] = fmaxf(acc, 0.f);
    }
    __syncthreads();
    if (tid < NBn) {
        float acc = b2[tid];
        for (int j = 0; j < GHn; j++) acc += hbuf[j] * w2p[tid*GHn + j];
        g_alpha[bc*NBn + tid] = 1.0f / (1.0f + expf(-acc));
    }
}

// ---------------- K2b: complex channel-mix GEMM (packed FFMA2) ----------------
__global__ void k2b_mix(const float* __restrict__ wr, const float* __restrict__ wi) {
    __shared__ float2 Wt1[32*16];   // (wr, wr)
    __shared__ float2 Wt2[32*16];   // (-wi, wi)
    __shared__ float2 Xt1[16*32];   // (xr, xi)
    __shared__ float2 Xt2[16*32];   // (xi, xr)
    __shared__ int    ibase[32];
    __shared__ int    okf[32];
    int kxi = g_kxi, kyi = g_kyi;
    int maskcnt = kxi * kyi;
    int Ntot = Bn * maskcnt;
    int n0 = blockIdx.y * 32;
    if (n0 >= Ntot) return;
    int c0 = blockIdx.x * 32;
    int tid = threadIdx.x;
    int tx = tid & 31, ty = tid >> 5;
    if (tid < 32) {
        int n = n0 + tid;
        if (n < Ntot) {
            int b = n / maskcnt, m = n % maskcnt;
            int hy = m / kyi, wx = m % kyi;
            int cc = (wx == 64) ? 64 : (brev7(wx) >> 1);
            ibase[tid] = b*Cn*Fn + hy*65 + cc;
            okf[tid] = 1;
        } else { ibase[tid] = 0; okf[tid] = 0; }
    }
    __syncthreads();
    u64 acc2[4];
    #pragma unroll
    for (int q = 0; q < 4; q++) acc2[q] = pk2(0.f, 0.f);
    for (int d0 = 0; d0 < Cn; d0 += 16) {
        #pragma unroll
        for (int i0 = 0; i0 < 2; i0++) {
            int i = tid + i0*256;
            int cc = i >> 4, dd = i & 15;
            int gi = (c0+cc)*Cn + d0+dd;
            float a = wr[gi], b = wi[gi];
            Wt1[i] = make_float2(a, a);
            Wt2[i] = make_float2(-b, b);
        }
        #pragma unroll
        for (int i0 = 0; i0 < 2; i0++) {
            int i = tid + i0*256;
            int dd = i >> 5, j = i & 31;
            float2 v = okf[j] ? g_Xf[(size_t)ibase[j] + (size_t)(d0+dd)*Fn]
                              : make_float2(0.f, 0.f);
            Xt1[i] = v;
            Xt2[i] = make_float2(v.y, v.x);
        }
        __syncthreads();
        #pragma unroll
        for (int dd = 0; dd < 16; dd++) {
            u64 xv1 = *(const u64*)&Xt1[dd*32 + tx];
            u64 xv2 = *(const u64*)&Xt2[dd*32 + tx];
            #pragma unroll
            for (int q = 0; q < 4; q++) {
                u64 w1 = *(const u64*)&Wt1[(ty + 8*q)*16 + dd];
                u64 w2 = *(const u64*)&Wt2[(ty + 8*q)*16 + dd];
                FMA2(acc2[q], w1, xv1, acc2[q]);
                FMA2(acc2[q], w2, xv2, acc2[q]);
            }
        }
        __syncthreads();
    }
    if (okf[tx]) {
        int n = n0 + tx;
        int b = n / maskcnt;
        int f = ibase[tx] - b*Cn*Fn;
        #pragma unroll
        for (int q = 0; q < 4; q++)
            g_Xm[((size_t)(b*Cn + c0 + ty + 8*q))*Fn + f] = upk2(acc2[q]);
    }
}

// ---------------- K3: gated spectrum -> irfft2 (warp-register) + conv ---------
__global__ void __launch_bounds__(NT, 2)
k3_ifft(const float* __restrict__ conv_w) {
    extern __shared__ float2 Z[];          // [128][P]
    __shared__ float2 tw[64];              // conjugated twiddles
    __shared__ float  a6[NBn];
    __shared__ float  cw[9];
    int tid = threadIdx.x;
    int l = tid & 31, w = tid >> 5;
    int bc = blockIdx.x;
    int c  = bc & (Cn-1);

    if (tid < 64) {
        float ang = 2.0f*3.14159265358979323846f*(float)tid/128.0f;
        float s_, c_; sincosf(ang, &s_, &c_);
        tw[tid] = make_float2(c_, s_);
    }
    if (tid < NBn) a6[tid] = g_alpha[bc*NBn + tid];
    if (tid < 9)   cw[tid] = conv_w[c*9 + tid];
    int kxi = g_kxi, kyi = g_kyi;
    __syncthreads();
    LaneTw T = load_lane_tw(tw, l);

    // gated spectrum into Z
    #pragma unroll
    for (int it = 0; it < (Fn + NT-1)/NT; it++) {
        int i = tid + it*NT;
        if (i < Fn) {
            int h = i / 65, cc = i - h*65;
            int kk = (cc == 64) ? 64 : brev7(2*cc);
            float al = a6[g_bandid[i]];
            float2 z;
            if (h < kxi && kk < kyi) {
                z = g_Xm[(size_t)bc*Fn + i];
                z.x *= al; z.y *= al;
            } else {
                z = g_Xf[(size_t)bc*Fn + i];
                float om = 1.0f - al;
                z.x *= om; z.y *= om;
            }
            Z[i] = z;
        }
    }
    __syncthreads();

    // inverse column FFTs (DIF, conj): natural in, brev-stored out
    for (int cc = w; cc < 65; cc += 16) {
        float2 x0 = Z[(l      )*P + cc];
        float2 x1 = Z[(32 + l )*P + cc];
        float2 x2 = Z[(64 + l )*P + cc];
        float2 x3 = Z[(96 + l )*P + cc];
        fft128_dif(x0, x1, x2, x3, T, l);
        Z[(l      )*P + cc] = x0;
        Z[(32 + l )*P + cc] = x1;
        Z[(64 + l )*P + cc] = x2;
        Z[(96 + l )*P + cc] = x3;
    }
    __syncthreads();

    // inverse row FFTs (DIT, conj): hermitian gather -> natural time out
    const float sc = 1.0f/128.0f;
    const float* xt0 = g_xt + (size_t)bc*HWn;
    float* sp0 = g_spec + (size_t)bc*HWn;
    #pragma unroll
    for (int i = 0; i < 8; i++) {
        int r = w + 16*i;
        const float2* zrow = Z + brev7(r)*P;
        float2 xr[4];
        #pragma unroll
        for (int q = 0; q < 4; q++) {
            int n = 32*q + l;
            int k = brev7(n);
            float2 v;
            if (k < 64)       v = zrow[n >> 1];
            else if (k == 64) v = zrow[64];
            else { int cc2 = brev7(128 - k) >> 1; v = zrow[cc2]; v.y = -v.y; }
            xr[q] = v;
        }
        fft128_dit(xr[0], xr[1], xr[2], xr[3], T, l);
        #pragma unroll
        for (int q = 0; q < 4; q++) {
            int wc = 32*q + l;
            float v = xr[q].x * sc;
            float cacc = 0.f;
            #pragma unroll
            for (int dy = -1; dy <= 1; dy++) {
                int hh = r + dy;
                if (hh < 0 || hh >= Hn) continue;
                #pragma unroll
                for (int dx = -1; dx <= 1; dx++) {
                    int ww = wc + dx;
                    if (ww >= 0 && ww < Wn)
                        cacc += cw[(dy+1)*3 + (dx+1)] * xt0[hh*Wn + ww];
                }
            }
            sp0[r*128 + wc] = v + cacc;
        }
    }
}

// ---------------- K4: pointwise GEMM (FFMA2, predup W) + spec add + LN --------
#define XS_STRIDE 66
__global__ void k4_final(const float* __restrict__ x,   const float* __restrict__ lin_b,
                         const float* __restrict__ tme,
                         const float* __restrict__ nww, const float* __restrict__ nwb,
                         const float* __restrict__ nbw, const float* __restrict__ nbb,
                         float* __restrict__ out) {
    extern __shared__ float sm[];
    float2* wsm2 = (float2*)sm;              // [32][256] pre-dup weight pairs (64 KB)
    float*  xs   = sm + 32*Cn*2;             // [256][XS_STRIDE]
    float*  ss   = xs + Cn*XS_STRIDE;        // [256][65]
    int tid = threadIdx.x;
    int b  = blockIdx.x >> 8;
    int p0 = (blockIdx.x & 255) << 6;

    for (int i = tid; i < 64*Cn; i += 256) {
        int pi = i >> 8, c = i & 255;
        xs[c*XS_STRIDE + pi] = x[((size_t)b*HWn + p0 + pi)*Cn + c];
    }
    for (int i = tid; i < Cn*64; i += 256) {
        int c = i >> 6, pi = i & 63;
        ss[c*65 + pi] = g_spec[((size_t)(b*Cn + c))*HWn + p0 + pi];
    }
    __syncthreads();

    int tc = tid & 31, tp = tid >> 5;
    u64 acc2[8][4];
    #pragma unroll
    for (int q = 0; q < 8; q++) {
        int cq = tc + 32*q;
        float lb = lin_b[cq];
        #pragma unroll
        for (int rp = 0; rp < 4; rp++)
            acc2[q][rp] = pk2(lb + ss[cq*65 + tp*8 + 2*rp],
                              lb + ss[cq*65 + tp*8 + 2*rp + 1]);
    }

    for (int d0 = 0; d0 < Cn; d0 += 32) {
        __syncthreads();
        for (int i = tid; i < 32*Cn; i += 256) {
            float wv = g_lwT[(size_t)d0*Cn + i];
            wsm2[i] = make_float2(wv, wv);
        }
        __syncthreads();
        #pragma unroll 4
        for (int dd = 0; dd < 32; dd++) {
            int d = d0 + dd;
            const u64* xp = (const u64*)&xs[d*XS_STRIDE + tp*8];
            u64 xv2[4];
            #pragma unroll
            for (int rp = 0; rp < 4; rp++) xv2[rp] = xp[rp];
            #pragma unroll
            for (int q = 0; q < 8; q++) {
                u64 w2 = *(const u64*)&wsm2[dd*Cn + tc + 32*q];
                #pragma unroll
                for (int rp = 0; rp < 4; rp++)
                    FMA2(acc2[q][rp], w2, xv2[rp], acc2[q][rp]);
            }
        }
    }

    float acc8[8][8];
    #pragma unroll
    for (int q = 0; q < 8; q++)
        #pragma unroll
        for (int rp = 0; rp < 4; rp++) {
            float2 v = upk2(acc2[q][rp]);
            acc8[q][2*rp]   = v.x;
            acc8[q][2*rp+1] = v.y;
        }

    float psum[8], psq[8];
    #pragma unroll
    for (int r = 0; r < 8; r++) { psum[r] = 0.f; psq[r] = 0.f; }
    #pragma unroll
    for (int q = 0; q < 8; q++)
        #pragma unroll
        for (int r = 0; r < 8; r++) {
            psum[r] += acc8[q][r];
            psq[r]  += acc8[q][r]*acc8[q][r];
        }
    #pragma unroll
    for (int off = 16; off > 0; off >>= 1)
        #pragma unroll
        for (int r = 0; r < 8; r++) {
            psum[r] += __shfl_xor_sync(0xffffffffu, psum[r], off);
            psq[r]  += __shfl_xor_sync(0xffffffffu, psq[r],  off);
        }
    float mean[8], rstd[8];
    #pragma unroll
    for (int r = 0; r < 8; r++) {
        mean[r] = psum[r] * (1.0f/256.0f);
        float var = psq[r] * (1.0f/256.0f) - mean[r]*mean[r];
        rstd[r] = rsqrtf(var + 1e-5f);
    }
    float t = tme[b];
    #pragma unroll
    for (int q = 0; q < 8; q++) {
        int cq = tc + 32*q;
        float wc = t * nww[cq] + nwb[cq];
        float bc_ = t * nbw[cq] + nbb[cq];
        #pragma unroll
        for (int r = 0; r < 8; r++) {
            int pi = tp*8 + r;
            out[((size_t)(b*HWn + p0 + pi))*Cn + cq] =
                wc * (acc8[q][r] - mean[r]) * rstd[r] + bc_;
        }
    }
}

// ------------------------------- launch ---------------------------------------
extern "C" void kernel_launch(void* const* d_in, const int* in_sizes, int n_in,
                              void* d_out, int out_size) {
    const float* x      = (const float*)d_in[0];
    const float* tme    = (const float*)d_in[1];
    const float* w_real = (const float*)d_in[2];
    const float* w_imag = (const float*)d_in[3];
    const float* conv_w = (const float*)d_in[4];
    const float* lin_w  = (const float*)d_in[5];
    const float* lin_b  = (const float*)d_in[6];
    const float* mlp_w1 = (const float*)d_in[7];
    const float* mlp_b1 = (const float*)d_in[8];
    const float* mlp_w2 = (const float*)d_in[9];
    const float* mlp_b2 = (const float*)d_in[10];
    const float* nww    = (const float*)d_in[11];
    const float* nwb    = (const float*)d_in[12];
    const float* nbw    = (const float*)d_in[13];
    const float* nbb    = (const float*)d_in[14];
    const float* kx     = (const float*)d_in[15];
    const float* ky     = (const float*)d_in[16];
    float* out = (float*)d_out;

    const int smem_fft = 128*P*8;                                       // 66,560 B
    const int smem_k4  = (32*Cn*2 + Cn*XS_STRIDE + Cn*65) * 4;          // 199,296 B
    cudaFuncSetAttribute(k1_fft,  cudaFuncAttributeMaxDynamicSharedMemorySize, smem_fft);
    cudaFuncSetAttribute(k3_ifft, cudaFuncAttributeMaxDynamicSharedMemorySize, smem_fft);
    cudaFuncSetAttribute(k4_final, cudaFuncAttributeMaxDynamicSharedMemorySize, smem_k4);

    k0_bands<<<1, 256>>>(kx, ky);
    k_trw<<<dim3(8,8), dim3(32,8)>>>(lin_w);

    dim3 trg(Cn/32, HWn/32, Bn);
    k_tr<<<trg, dim3(32,8)>>>(x);

    k1_fft<<<Bn*Cn, NT, smem_fft>>>(mlp_w1, mlp_b1, mlp_w2, mlp_b2);

    dim3 mixg(Cn/32, (Bn*Fn + 31)/32);
    k2b_mix<<<mixg, 256>>>(w_real, w_imag);

    k3_ifft<<<Bn*Cn, NT, smem_fft>>>(conv_w);

    k4_final<<<Bn*(HWn/64), 256, smem_k4>>>(x, lin_b, tme, nww, nwb, nbw, nbb, out);
}